// round 2
// baseline (speedup 1.0000x reference)
#include <cuda_runtime.h>
#include <cuda_bf16.h>

// Problem constants (fixed by the dataset)
#define BB   16
#define SS   2048
#define DD   240
#define EE   8
#define TT   (BB * SS)        // 32768 tokens

// GEMM tiling
#define TM   64               // tokens per tile
#define TN   80               // outputs per tile (240 = 3 * 80)
#define KC   48               // K chunk (240 = 5 * 48)
#define KSTR (KC + 4)         // smem row stride in floats (52: 16B aligned)

// Scratch (device globals — no allocation allowed in kernel_launch)
__device__ int   g_cnt[EE];
__device__ int   g_tok[EE][TT];
__device__ float g_gw [EE][TT];

// ---------------------------------------------------------------------------
// Kernel 0: zero output + per-expert counters
// ---------------------------------------------------------------------------
__global__ void zero_kernel(float4* __restrict__ out4, int n4) {
    int i = blockIdx.x * blockDim.x + threadIdx.x;
    if (i < n4) out4[i] = make_float4(0.f, 0.f, 0.f, 0.f);
    if (blockIdx.x == 0 && threadIdx.x < EE) g_cnt[threadIdx.x] = 0;
}

// ---------------------------------------------------------------------------
// Kernel 1: gating — one warp per token.
// logits = x @ gate_w^T + gate_b ; top-2 ; renormalized weights == 2-way
// softmax over the top-2 logits. Scatter (token, weight) into per-expert lists.
// ---------------------------------------------------------------------------
__global__ __launch_bounds__(256)
void gate_kernel(const float* __restrict__ x,
                 const float* __restrict__ gw,
                 const float* __restrict__ gb) {
    int warp = (blockIdx.x * blockDim.x + threadIdx.x) >> 5;
    int lane = threadIdx.x & 31;
    if (warp >= TT) return;

    const float* xp = x + (long)warp * DD;
    float xv[8];
#pragma unroll
    for (int i = 0; i < 8; i++) {
        int d = lane + 32 * i;
        xv[i] = (d < DD) ? xp[d] : 0.f;
    }

    float l[EE];
#pragma unroll
    for (int e = 0; e < EE; e++) {
        const float* wp = gw + e * DD;
        float s = 0.f;
#pragma unroll
        for (int i = 0; i < 8; i++) {
            int d = lane + 32 * i;
            s += xv[i] * ((d < DD) ? wp[d] : 0.f);
        }
#pragma unroll
        for (int o = 16; o > 0; o >>= 1) s += __shfl_xor_sync(0xffffffffu, s, o);
        l[e] = s + gb[e];
    }

    if (lane == 0) {
        // top-1 (earliest index on ties, matching jax top_k)
        int b1 = 0;
#pragma unroll
        for (int e = 1; e < EE; e++) if (l[e] > l[b1]) b1 = e;
        // top-2
        int b2 = (b1 == 0) ? 1 : 0;
#pragma unroll
        for (int e = 0; e < EE; e++) {
            if (e == b1 || e == b2) continue;
            if (l[e] > l[b2]) b2 = e;
        }
        float m  = fmaxf(l[b1], l[b2]);
        float e1 = __expf(l[b1] - m);
        float e2 = __expf(l[b2] - m);
        float inv = 1.f / (e1 + e2);
        int p1 = atomicAdd(&g_cnt[b1], 1);
        g_tok[b1][p1] = warp;  g_gw[b1][p1] = e1 * inv;
        int p2 = atomicAdd(&g_cnt[b2], 1);
        g_tok[b2][p2] = warp;  g_gw[b2][p2] = e2 * inv;
    }
}

// ---------------------------------------------------------------------------
// Kernel 2: grouped expert GEMM.
// grid = (T/TM, 240/TN, E). Block: 256 threads, 4x5 register tile.
// out[t, :] += w_t * (x[t, :] @ W_e^T + b_e)  via fp32 atomicAdd (2 adds per
// element, commutative -> deterministic).
// ---------------------------------------------------------------------------
__global__ __launch_bounds__(256)
void moe_gemm_kernel(const float* __restrict__ x,
                     const float* __restrict__ ew,
                     const float* __restrict__ eb,
                     float* __restrict__ out) {
    int e   = blockIdx.z;
    int cnt = g_cnt[e];
    int m0  = blockIdx.x * TM;
    if (m0 >= cnt) return;
    int n0  = blockIdx.y * TN;

    __shared__ float Xs[TM][KSTR];
    __shared__ float Ws[TN][KSTR];
    __shared__ int   ts[TM];
    __shared__ float ws[TM];

    int tid = threadIdx.x;
    if (tid < TM) {
        int gr = m0 + tid;
        if (gr < cnt) { ts[tid] = g_tok[e][gr]; ws[tid] = g_gw[e][gr]; }
        else          { ts[tid] = -1;           ws[tid] = 0.f; }
    }
    __syncthreads();

    int tm = tid & 15;   // m group: m = tm + 16*i
    int tn = tid >> 4;   // n group: n = tn + 16*j
    float acc[4][5] = {};

    const float* wbase = ew + (long)e * DD * DD;

    for (int k0 = 0; k0 < DD; k0 += KC) {
        // load X tile: TM x KC as float4 (TM * KC/4 = 768 vectors)
        for (int idx = tid; idx < TM * (KC / 4); idx += 256) {
            int r = idx / (KC / 4);
            int c = idx % (KC / 4);
            float4 v = make_float4(0.f, 0.f, 0.f, 0.f);
            int t = ts[r];
            if (t >= 0) v = *(const float4*)(x + (long)t * DD + k0 + c * 4);
            *(float4*)&Xs[r][c * 4] = v;
        }
        // load W tile: TN x KC as float4 (TN * KC/4 = 960 vectors)
        for (int idx = tid; idx < TN * (KC / 4); idx += 256) {
            int r = idx / (KC / 4);
            int c = idx % (KC / 4);
            float4 v = *(const float4*)(wbase + (long)(n0 + r) * DD + k0 + c * 4);
            *(float4*)&Ws[r][c * 4] = v;
        }
        __syncthreads();

#pragma unroll
        for (int kk = 0; kk < KC; kk += 4) {
            float4 xm[4];
            float4 wn[5];
#pragma unroll
            for (int i = 0; i < 4; i++) xm[i] = *(const float4*)&Xs[tm + 16 * i][kk];
#pragma unroll
            for (int j = 0; j < 5; j++) wn[j] = *(const float4*)&Ws[tn + 16 * j][kk];
#pragma unroll
            for (int i = 0; i < 4; i++) {
#pragma unroll
                for (int j = 0; j < 5; j++) {
                    acc[i][j] += xm[i].x * wn[j].x;
                    acc[i][j] += xm[i].y * wn[j].y;
                    acc[i][j] += xm[i].z * wn[j].z;
                    acc[i][j] += xm[i].w * wn[j].w;
                }
            }
        }
        __syncthreads();
    }

    // epilogue: out[t, n0+n] += w * (acc + b_e[n0+n])
#pragma unroll
    for (int i = 0; i < 4; i++) {
        int r = tm + 16 * i;
        int t = ts[r];
        if (t < 0) continue;
        float w = ws[r];
        float* op = out + (long)t * DD + n0;
        const float* bp = eb + e * DD + n0;
#pragma unroll
        for (int j = 0; j < 5; j++) {
            int n = tn + 16 * j;
            atomicAdd(&op[n], w * (acc[i][j] + bp[n]));
        }
    }
}

// ---------------------------------------------------------------------------
extern "C" void kernel_launch(void* const* d_in, const int* in_sizes, int n_in,
                              void* d_out, int out_size) {
    const float* x  = (const float*)d_in[0];   // [B,S,D]
    const float* gw = (const float*)d_in[1];   // [E,D]
    const float* gb = (const float*)d_in[2];   // [E]
    const float* ew = (const float*)d_in[3];   // [E,D,D]
    const float* eb = (const float*)d_in[4];   // [E,D]
    float* out = (float*)d_out;                // [B,S,D] fp32

    // 1) zero output + expert counters
    int n4 = out_size / 4;                     // out_size = 7,864,320 (mult of 4)
    zero_kernel<<<(n4 + 255) / 256, 256>>>((float4*)out, n4);

    // 2) gating: one warp per token
    gate_kernel<<<(TT * 32) / 256, 256>>>(x, gw, gb);

    // 3) grouped expert GEMM
    dim3 grid(TT / TM, DD / TN, EE);           // (512, 3, 8)
    moe_gemm_kernel<<<grid, 256>>>(x, ew, eb, out);
}